// round 10
// baseline (speedup 1.0000x reference)
#include <cuda_runtime.h>

#define NV 256   // vertices
#define KD 16    // degree
#define HD 32    // hidden
#define NT 512   // threads per CTA

// ---------------- globals ----------------
__device__ float g_F1[NV * 256 * HD];       // layer-1 output, 8 MB
__device__ unsigned g_flag[NV];             // per-vertex publish flag (epoch-stamped)
__device__ unsigned g_epoch;
__device__ unsigned g_done;
__device__ float g_acc;

typedef unsigned long long ull;

__device__ __forceinline__ ull pack2(float x) {
    ull r; asm("mov.b64 %0, {%1, %1};" : "=l"(r) : "f"(x)); return r;
}
__device__ __forceinline__ ull pack2f(float lo, float hi) {
    ull r; asm("mov.b64 %0, {%1, %2};" : "=l"(r) : "f"(lo), "f"(hi)); return r;
}
__device__ __forceinline__ void unpack2(ull v, float& lo, float& hi) {
    asm("mov.b64 {%0, %1}, %2;" : "=f"(lo), "=f"(hi) : "l"(v));
}
__device__ __forceinline__ void dfma(ull& acc, ull a, ull b) {
    asm("fma.rn.f32x2 %0, %1, %2, %0;" : "+l"(acc) : "l"(a), "l"(b));
}
__device__ __forceinline__ ull addx2(ull a, ull b) {
    ull r; asm("add.rn.f32x2 %0, %1, %2;" : "=l"(r) : "l"(a), "l"(b)); return r;
}
__device__ __forceinline__ void cp16(float* sdst, const float4* gsrc) {
    unsigned s = (unsigned)__cvta_generic_to_shared(sdst);
    asm volatile("cp.async.cg.shared.global [%0], [%1], 16;" :: "r"(s), "l"(gsrc));
}

// ---------------- smem layout (floats) ----------------
#define OFF_W     0          // 3072 : layer1 [6][512]; later layer2 [Wsb|W2b|W15] each 1024
#define OFF_T0    3072       // 8192 : tile0 (layer1 scratch aliases; st-exchange in epilogue)
#define OFF_T1    11264      // 8192 : tile1
#define OFF_GT    19456      // 1728 : sGt triple buffer [3][16][36]
#define OFF_DG    21184      // 1728 : sDiag triple buffer
#define OFF_SAB   22912      // 512
#define OFF_STB   23424      // 512
#define OFF_SAL   23936      // 32
#define OFF_YB    23968      // 1088 : ull[2][272]; OVERLAY: sU(512)+sD(32)+sRED(16) post-pickup
#define OFF_INT   25056      // nbr16,qm16,vm16,cnt16,misc4,M(64w) = 132 floats
#define SMEM_FLOATS (25056 + 132)
#define SMEM_BYTES  (SMEM_FLOATS * 4)

__device__ __forceinline__ void issue_tile(int t, float* buf, int tid, const int* sNbr) {
    const float4* src = (const float4*)(g_F1 + (size_t)sNbr[t] * 8192);
#pragma unroll
    for (int k = 0; k < 4; k++) {
        int g = k * 512 + tid;
        int r = g >> 3, c4 = g & 7;
        cp16(buf + r * 32 + ((c4 ^ (r & 7)) << 2), src + g);
    }
    asm volatile("cp.async.commit_group;");
}

// phase A: G'[a][c] (a-indexed, zero-filled when invalid) + diag extraction + stb accum.
// thread mapping: aA = warp, qg = q-quarter, c4A = float4 col.
__device__ __forceinline__ void phaseA512(int t, const float4* bufv, float* sGt, float* sDg,
                                          const unsigned* sQM, const signed char* sM,
                                          int aA, int qg, int c4A, ull& stbA, ull& stbB) {
    int par = (t % 3) * 576;
    unsigned qm = sQM[t];
    int pA = sM[t * 16 + aA];
    ull acc0 = 0ull, acc1 = 0ull;
    if (pA >= 0) {
        int rbase = pA * 16 + qg * 4;
#pragma unroll
        for (int k = 0; k < 4; k++) {
            if (qm & (1u << (qg * 4 + k))) {
                int r = rbase + k;
                longlong2 v = *(const longlong2*)(bufv + r * 8 + (c4A ^ (r & 7)));
                acc0 = addx2(acc0, (ull)v.x);
                acc1 = addx2(acc1, (ull)v.y);
            }
        }
    }
    float f0, f1, f2, f3;
    unpack2(acc0, f0, f1);
    unpack2(acc1, f2, f3);
    f0 += __shfl_xor_sync(0xffffffffu, f0, 8);
    f1 += __shfl_xor_sync(0xffffffffu, f1, 8);
    f2 += __shfl_xor_sync(0xffffffffu, f2, 8);
    f3 += __shfl_xor_sync(0xffffffffu, f3, 8);
    f0 += __shfl_xor_sync(0xffffffffu, f0, 16);
    f1 += __shfl_xor_sync(0xffffffffu, f1, 16);
    f2 += __shfl_xor_sync(0xffffffffu, f2, 16);
    f3 += __shfl_xor_sync(0xffffffffu, f3, 16);
    if (qg == 0) {
        stbA = addx2(stbA, pack2f(f0, f1));
        stbB = addx2(stbB, pack2f(f2, f3));
        float4 o; o.x = f0; o.y = f1; o.z = f2; o.w = f3;
        *(float4*)(sGt + par + aA * 36 + c4A * 4) = o;
    } else if (qg == 1) {
        float4 dv; dv.x = dv.y = dv.z = dv.w = 0.0f;
        if (pA >= 0) {
            int rd = pA * 17;
            longlong2 v = *(const longlong2*)(bufv + rd * 8 + (c4A ^ (rd & 7)));
            float a, b;
            unpack2((ull)v.x, a, b); dv.x = a; dv.y = b;
            unpack2((ull)v.y, a, b); dv.z = a; dv.w = b;
        }
        *(float4*)(sDg + par + aA * 36 + c4A * 4) = dv;
    }
}

// st accumulation: thread (i,j,hh) reads its c-half of row (pa,pb)
__device__ __forceinline__ void stGather512(int t, const float4* bufv, const signed char* sM,
                                            int i, int j, int hh, ull* st2) {
    int pa = sM[t * 16 + i], pb = sM[t * 16 + j];
    if ((pa | pb) >= 0) {
        int r = pa * 16 + pb;
#pragma unroll
        for (int k = 0; k < 4; k++) {
            int c4 = hh * 4 + k;
            longlong2 v = *(const longlong2*)(bufv + r * 8 + (c4 ^ (r & 7)));
            st2[2 * k + 0] = addx2(st2[2 * k + 0], (ull)v.x);
            st2[2 * k + 1] = addx2(st2[2 * k + 1], (ull)v.y);
        }
    }
}

// collab gb/dg row-op: output (row tp, col jcol, h-pair hp); full 32 c.
__device__ __forceinline__ ull collab_one(int tp, int jcol, int hp,
                                          const float* sGt, const float* sDg,
                                          const float* sW, const signed char* sM) {
    int slot = (tp % 3) * 576;
    int pj = sM[tp * 16 + jcol];
    ull a0 = 0ull, a1 = 0ull;
    if (pj >= 0) {
        const float* gr = sGt + slot + jcol * 36;
        const float* dr = sDg + slot + jcol * 36;
        const float* w0b = sW + 2 * hp;           // Wsb
        const float* w5b = sW + 2048 + 2 * hp;    // W15
#pragma unroll
        for (int c4 = 0; c4 < 8; c4++) {
            float4 g4 = *(const float4*)(gr + c4 * 4);
            float4 d4 = *(const float4*)(dr + c4 * 4);
            float gv[4] = {g4.x, g4.y, g4.z, g4.w};
            float dv[4] = {d4.x, d4.y, d4.z, d4.w};
#pragma unroll
            for (int cl = 0; cl < 4; cl++) {
                int c = c4 * 4 + cl;
                dfma(a0, pack2(gv[cl]), *(const ull*)(w0b + c * 32));
                dfma(a1, pack2(dv[cl]), *(const ull*)(w5b + c * 32));
            }
        }
    }
    return addx2(a0, a1);
}

__global__ __launch_bounds__(NT, 2) void ccn_fused(const int* __restrict__ nbrs,
                                                   const float* __restrict__ X,
                                                   const float* __restrict__ W1,
                                                   const float* __restrict__ b1,
                                                   const float* __restrict__ W2,
                                                   const float* __restrict__ b2,
                                                   const float* __restrict__ fcw,
                                                   const float* __restrict__ fcb,
                                                   float* __restrict__ out) {
    extern __shared__ float smem[];
    float* sW    = smem + OFF_W;
    float* tile0 = smem + OFF_T0;
    float* tile1 = smem + OFF_T1;
    float* sGt   = smem + OFF_GT;    // [3][16][36]
    float* sDg   = smem + OFF_DG;    // [3][16][36]
    float* sSAB  = smem + OFF_SAB;   // [16][32]
    float* sSTB  = smem + OFF_STB;   // [16][32]
    float* sSAL  = smem + OFF_SAL;
    ull*   sYB   = (ull*)(smem + OFF_YB);     // [2][272]; overlaid post-pickup
    float* sU    = smem + OFF_YB;
    float* sD    = sU + 512;
    float* sRED  = sU + 544;
    int*      sNbr = (int*)(smem + OFF_INT);
    unsigned* sQM  = (unsigned*)(sNbr + 16);
    unsigned* sVM  = (unsigned*)(sQM + 16);
    float*    sCnt = (float*)(sVM + 16);
    unsigned* sMisc = (unsigned*)(sCnt + 16);
    signed char* sM = (signed char*)(sMisc + 4);     // 256

    // layer-1 scratch aliases inside tile0
    float* sXn  = tile0;          // 256
    float* sAB1 = tile0 + 256;    // 256
    float* sTB1 = tile0 + 512;    // 256
    float* sAL1 = tile0 + 768;    // 16
    float* sU1  = tile0 + 784;    // 512
    float* sD1  = tile0 + 1296;   // 32
    float* sB1  = tile0 + 1328;   // 32

    int n = blockIdx.x, tid = threadIdx.x;
    int i    = tid >> 5;          // warp id = row i (also phase-A row aA, collab jcol)
    int j    = (tid >> 1) & 15;   // column
    int hh   = tid & 1;           // h-half
    int hoff = hh * 16;
    int qg   = (tid >> 3) & 3;    // phase-A q quarter
    int c4A  = tid & 7;           // phase-A / stb float4 col

    // ============ stage 0 ============
    if (tid < 256) {
        int t = tid >> 4, a = tid & 15;
        int jv = nbrs[n * 16 + t];
        int target = nbrs[n * 16 + a];
        int r = -1;
#pragma unroll
        for (int p = 0; p < 16; p++)
            if (nbrs[jv * 16 + p] == target) r = p;
        sM[tid] = (signed char)r;
        sXn[tid] = X[jv * 16 + a];
    }
    if (tid < 16) sNbr[tid] = nbrs[n * 16 + tid];
    // Wc1 (C=16): slot0=16*(W0+W6..14)+W5, 1=W1, 2=16*W2, 3=W3, 4=W4, 5=W15
    {
        int c = tid >> 5, h = tid & 31;   // 512 entries exactly
        float s = W1[(0 * 16 + c) * 32 + h];
#pragma unroll
        for (int m = 6; m < 15; m++) s += W1[(m * 16 + c) * 32 + h];
        sW[0 * 512 + c * 32 + h] = 16.0f * s + W1[(5 * 16 + c) * 32 + h];
        sW[1 * 512 + c * 32 + h] = W1[(1 * 16 + c) * 32 + h];
        sW[2 * 512 + c * 32 + h] = 16.0f * W1[(2 * 16 + c) * 32 + h];
        sW[3 * 512 + c * 32 + h] = W1[(3 * 16 + c) * 32 + h];
        sW[4 * 512 + c * 32 + h] = W1[(4 * 16 + c) * 32 + h];
        sW[5 * 512 + c * 32 + h] = W1[(15 * 16 + c) * 32 + h];
    }
    if (tid < HD) sB1[tid] = b1[tid];
    if (tid == 0) sMisc[0] = g_epoch;
    __syncthreads();
    if (tid < 16) {
        unsigned vm = 0, qm = 0;
#pragma unroll
        for (int a = 0; a < 16; a++) {
            int p = sM[tid * 16 + a];
            if (p >= 0) { vm |= 1u << a; qm |= 1u << p; }
        }
        sVM[tid] = vm;
        sQM[tid] = qm;
        sCnt[tid] = (float)__popc(vm);
    }
    __syncthreads();

    // ============ layer 1 (F0[n,p,q,c] = X[n,c] closed forms) ============
    if (tid < 256) {
        int t2 = tid >> 4, c2 = tid & 15;
        sAB1[tid] = sCnt[t2] * sCnt[t2] * sXn[tid];
        float s = 0.0f;
#pragma unroll
        for (int t = 0; t < 16; t++)
            if ((sVM[t] >> t2) & 1) s += sCnt[t] * sXn[t * 16 + c2];
        sTB1[tid] = s;
    }
    __syncthreads();
    if (tid < 16) {
        float s = 0.0f;
#pragma unroll
        for (int t = 0; t < 16; t++) s += sAB1[t * 16 + tid];
        sAL1[tid] = s;
    }
    __syncthreads();
    {   // U1: one (row,h) per thread
        int row = tid >> 5, h = tid & 31;
        float u = 0.0f;
#pragma unroll
        for (int c = 0; c < 16; c++)
            u += sAB1[row * 16 + c] * sW[1 * 512 + c * 32 + h]
               + sTB1[row * 16 + c] * sW[3 * 512 + c * 32 + h];
        sU1[row * 32 + h] = u;
    }
    if (tid < HD) {
        float s = 0.0f;
#pragma unroll
        for (int c = 0; c < 16; c++) s += sAL1[c] * sW[4 * 512 + c * 32 + tid];
        sD1[tid] = s;
    }
    __syncthreads();
    {
        float st1[16];
#pragma unroll
        for (int c = 0; c < 16; c++) st1[c] = 0.0f;
#pragma unroll
        for (int t = 0; t < 16; t++) {
            unsigned vm = sVM[t];
            if (((vm >> i) & (vm >> j)) & 1) {
                const float4* xr = (const float4*)(sXn + t * 16);
#pragma unroll
                for (int c4 = 0; c4 < 4; c4++) {
                    float4 v = xr[c4];
                    st1[c4 * 4 + 0] += v.x; st1[c4 * 4 + 1] += v.y;
                    st1[c4 * 4 + 2] += v.z; st1[c4 * 4 + 3] += v.w;
                }
            }
        }
        ull y1[8];
#pragma unroll
        for (int k = 0; k < 8; k++) {
            ull u = *(const ull*)(sU1 + i * 32 + hoff + 2 * k);
            ull b = *(const ull*)(sB1 + hoff + 2 * k);
            y1[k] = addx2(u, b);
            if (i == j) y1[k] = addx2(y1[k], *(const ull*)(sD1 + hoff + 2 * k));
        }
        bool val = (sM[i * 16 + j] >= 0);
        float cnti = sCnt[i];
#pragma unroll
        for (int c = 0; c < 16; c++) {
            float xv = val ? sXn[i * 16 + c] : 0.0f;
            ull a0 = pack2(st1[c]);
            ull a1 = pack2(cnti * xv);
            ull a2 = pack2(xv);
            const ull* w2r = (const ull*)(sW + 2 * 512 + c * 32 + hoff);
            const ull* w0r = (const ull*)(sW + 0 * 512 + c * 32 + hoff);
            const ull* w5r = (const ull*)(sW + 5 * 512 + c * 32 + hoff);
#pragma unroll
            for (int k = 0; k < 8; k++) {
                dfma(y1[k], a0, w2r[k]);
                dfma(y1[k], a1, w0r[k]);
                dfma(y1[k], a2, w5r[k]);
            }
        }
        float* dst = g_F1 + (size_t)(n * 256 + i * 16 + j) * 32 + hoff;
#pragma unroll
        for (int q = 0; q < 4; q++) {
            float4 o;
            unpack2(y1[2 * q + 0], o.x, o.y);
            unpack2(y1[2 * q + 1], o.z, o.w);
            o.x = fmaxf(o.x, 0.0f); o.y = fmaxf(o.y, 0.0f);
            o.z = fmaxf(o.z, 0.0f); o.w = fmaxf(o.w, 0.0f);
            ((float4*)dst)[q] = o;
        }
    }
    __threadfence();
    __syncthreads();
    if (tid == 0) atomicExch(&g_flag[n], sMisc[0] + 1);   // publish

    // ============ layer-2 weights: Wsb | W2b(16x folded) | W15 (overwrites layer-1 sW) ============
#pragma unroll
    for (int rep = 0; rep < 2; rep++) {
        int idx = tid + rep * 512;
        int c = idx >> 5, h = idx & 31;
        float s = W2[(0 * 32 + c) * 32 + h];
#pragma unroll
        for (int m = 6; m < 15; m++) s += W2[(m * 32 + c) * 32 + h];
        sW[c * 32 + h]        = 16.0f * s + W2[(5 * 32 + c) * 32 + h];
        sW[1024 + c * 32 + h] = 16.0f * W2[(2 * 32 + c) * 32 + h];
        sW[2048 + c * 32 + h] = W2[(15 * 32 + c) * 32 + h];
    }
    if (tid < 16) {
        unsigned tgt = sMisc[0] + 1;
        const unsigned* fp = &g_flag[sNbr[tid]];
        unsigned v;
        do {
            asm volatile("ld.acquire.gpu.global.u32 %0, [%1];" : "=r"(v) : "l"(fp) : "memory");
        } while (v != tgt);
    }
    __syncthreads();

    // ============ layer 2 main loop (pair-collab, all phases balanced over 512 threads) ============
    issue_tile(0, tile0, tid, sNbr);

    ull st2[8];
#pragma unroll
    for (int c = 0; c < 8; c++) st2[c] = 0ull;
    ull y[8];
#pragma unroll
    for (int k = 0; k < 8; k++) y[k] = 0ull;
    ull stbA = 0ull, stbB = 0ull;  // meaningful for qg==0 threads

    int tsel = (tid >> 4) & 1;
    int hp   = tid & 15;

    for (int tt = 0; tt < 8; tt++) {
        int t0 = 2 * tt, t1 = 2 * tt + 1;
        // ---- even iteration t0 (tile in tile0) ----
        {
            const float4* bufv = (const float4*)tile0;
            asm volatile("cp.async.wait_group 0;");
            __syncthreads();
            issue_tile(t1, tile1, tid, sNbr);
            if (tt >= 1) {   // collab tiles t0-1 (tsel 0), t0-2 (tsel 1)
                int tp = tsel ? (t0 - 2) : (t0 - 1);
                sYB[tsel * 272 + i * 17 + hp] = collab_one(tp, i, hp, sGt, sDg, sW, sM);
            }
            phaseA512(t0, bufv, sGt, sDg, sQM, sM, i, qg, c4A, stbA, stbB);
            stGather512(t0, bufv, sM, i, j, hh, st2);
            if (tt >= 1 && tid < 32) {
                const float* gp = sGt + ((t0 - 1) % 3) * 576;
                float s = 0.0f;
#pragma unroll
                for (int a = 0; a < 16; a++) s += gp[a * 36 + tid];
                sSAB[(t0 - 1) * 32 + tid] = s;
            }
        }
        // ---- odd iteration t1 (tile in tile1) ----
        {
            const float4* bufv = (const float4*)tile1;
            asm volatile("cp.async.wait_group 0;");
            __syncthreads();
            if (t1 < 15) issue_tile(t1 + 1, tile0, tid, sNbr);
            if (tt >= 1) {   // pickup
                if (i == t0 - 1) {
#pragma unroll
                    for (int k = 0; k < 8; k++)
                        y[k] = addx2(y[k], sYB[j * 17 + hh * 8 + k]);
                }
                if (i == t0 - 2) {
#pragma unroll
                    for (int k = 0; k < 8; k++)
                        y[k] = addx2(y[k], sYB[272 + j * 17 + hh * 8 + k]);
                }
            }
            phaseA512(t1, bufv, sGt, sDg, sQM, sM, i, qg, c4A, stbA, stbB);
            stGather512(t1, bufv, sM, i, j, hh, st2);
            if (tid < 32) {
                const float* gp = sGt + (t0 % 3) * 576;
                float s = 0.0f;
#pragma unroll
                for (int a = 0; a < 16; a++) s += gp[a * 36 + tid];
                sSAB[t0 * 32 + tid] = s;
            }
        }
    }

    // ============ epilogue ============
    __syncthreads();                           // E1: phaseA(15) visible, st2/stb final, tile0 free
    {
        int tp = tsel ? 14 : 15;               // slots 2 and 0 resp.
        sYB[tsel * 272 + i * 17 + hp] = collab_one(tp, i, hp, sGt, sDg, sW, sM);
    }
    if (tid < 32) {                            // sum_ab(15), slot 0
        float s = 0.0f;
#pragma unroll
        for (int a = 0; a < 16; a++) s += sGt[a * 36 + tid];
        sSAB[15 * 32 + tid] = s;
    }
    if (qg == 0) {                             // write sum_tb
        float4 o;
        unpack2(stbA, o.x, o.y);
        unpack2(stbB, o.z, o.w);
        *(float4*)(sSTB + i * 32 + c4A * 4) = o;
    }
    {                                          // st exchange into tile0 (stride 36)
        int pos = i * 16 + j;
#pragma unroll
        for (int k = 0; k < 4; k++) {
            float4 o;
            unpack2(st2[2 * k + 0], o.x, o.y);
            unpack2(st2[2 * k + 1], o.z, o.w);
            *(float4*)(tile0 + pos * 36 + hoff + k * 4) = o;
        }
    }
    __syncthreads();                           // E2
    if (i == 15) {
#pragma unroll
        for (int k = 0; k < 8; k++) y[k] = addx2(y[k], sYB[j * 17 + hh * 8 + k]);
    }
    if (i == 14) {
#pragma unroll
        for (int k = 0; k < 8; k++) y[k] = addx2(y[k], sYB[272 + j * 17 + hh * 8 + k]);
    }
    if (tid < 32) {
        float s = 0.0f;
#pragma unroll
        for (int t = 0; t < 16; t++) s += sSAB[t * 32 + tid];
        sSAL[tid] = s;
    }
    __syncthreads();                           // E3: sYB reads done; overlay writable
    {   // U[row][h] into overlay (W1b/W3b slices straight from global W2, L1-broadcast)
        int row = tid >> 5, h = tid & 31;
        float u = 0.0f;
#pragma unroll
        for (int c = 0; c < 32; c++)
            u += sSAB[row * 32 + c] * __ldg(&W2[(1 * 32 + c) * 32 + h])
               + sSTB[row * 32 + c] * __ldg(&W2[(3 * 32 + c) * 32 + h]);
        sU[row * 32 + h] = u;
    }
    if (tid < 32) {
        float d = 0.0f;
#pragma unroll
        for (int c = 0; c < 32; c++) d += sSAL[c] * __ldg(&W2[(4 * 32 + c) * 32 + tid]);
        sD[tid] = d;
    }
    __syncthreads();                           // E4

    // ---- st GEMM (W2b smem, 16x already folded), h-half per thread ----
    {
        const float* stRow = tile0 + (i * 16 + j) * 36;
#pragma unroll
        for (int c4 = 0; c4 < 8; c4++) {
            float4 s4 = *(const float4*)(stRow + c4 * 4);
            float sv[4] = {s4.x, s4.y, s4.z, s4.w};
#pragma unroll
            for (int cl = 0; cl < 4; cl++) {
                const ull* w2r = (const ull*)(sW + 1024 + (c4 * 4 + cl) * 32 + hoff);
                ull a = pack2(sv[cl]);
#pragma unroll
                for (int k = 0; k < 4; k++) {
                    longlong2 w2 = ((const longlong2*)w2r)[k];
                    dfma(y[2 * k + 0], a, (ull)w2.x);
                    dfma(y[2 * k + 1], a, (ull)w2.y);
                }
            }
        }
    }

    // ---- finalize: add U/D/bias, relu, dot fc, reduce ----
    float loc = 0.0f;
#pragma unroll
    for (int k = 0; k < 8; k++) {
        ull u = *(const ull*)(sU + i * 32 + hoff + 2 * k);
        ull bv = *(const ull*)(b2 + hoff + 2 * k);
        ull v = addx2(y[k], addx2(u, bv));
        if (i == j) v = addx2(v, *(const ull*)(sD + hoff + 2 * k));
        float lo, hi;
        unpack2(v, lo, hi);
        float w0, w1;
        unpack2(*(const ull*)(fcw + hoff + 2 * k), w0, w1);
        loc += fmaxf(lo, 0.0f) * w0 + fmaxf(hi, 0.0f) * w1;
    }
#pragma unroll
    for (int o = 16; o > 0; o >>= 1) loc += __shfl_xor_sync(0xffffffffu, loc, o);
    if ((tid & 31) == 0) sRED[tid >> 5] = loc;
    __syncthreads();
    if (tid == 0) {
        float s = 0.0f;
#pragma unroll
        for (int w = 0; w < 16; w++) s += sRED[w];
        atomicAdd(&g_acc, s);
        __threadfence();
        unsigned prev = atomicAdd(&g_done, 1);
        if (prev == NV - 1) {
            float tot = atomicAdd(&g_acc, 0.0f);
            out[0] = tot + fcb[0];
            g_acc = 0.0f;
            g_done = 0;
            g_epoch = sMisc[0] + 1;
            __threadfence();
        }
    }
}

extern "C" void kernel_launch(void* const* d_in, const int* in_sizes, int n_in,
                              void* d_out, int out_size) {
    const float* X   = (const float*)d_in[0];
    const int*   nbr = (const int*)d_in[1];
    const float* W1  = (const float*)d_in[2];
    const float* b1  = (const float*)d_in[3];
    const float* W2  = (const float*)d_in[4];
    const float* b2  = (const float*)d_in[5];
    const float* fcw = (const float*)d_in[6];
    const float* fcb = (const float*)d_in[7];
    float* out = (float*)d_out;

    cudaFuncSetAttribute(ccn_fused, cudaFuncAttributeMaxDynamicSharedMemorySize, SMEM_BYTES);
    ccn_fused<<<NV, NT, SMEM_BYTES>>>(nbr, X, W1, b1, W2, b2, fcw, fcb, out);
}

// round 12
// speedup vs baseline: 1.2427x; 1.2427x over previous
#include <cuda_runtime.h>

#define NV 256   // vertices
#define KD 16    // degree
#define HD 32    // hidden

// ---------------- globals ----------------
__device__ float g_F1[NV * 256 * HD];       // layer-1 output, 8 MB
__device__ unsigned g_flag[NV];             // per-vertex publish flag (epoch-stamped)
__device__ unsigned g_epoch;
__device__ unsigned g_done;
__device__ float g_acc;

typedef unsigned long long ull;

__device__ __forceinline__ ull pack2(float x) {
    ull r; asm("mov.b64 %0, {%1, %1};" : "=l"(r) : "f"(x)); return r;
}
__device__ __forceinline__ ull pack2f(float lo, float hi) {
    ull r; asm("mov.b64 %0, {%1, %2};" : "=l"(r) : "f"(lo), "f"(hi)); return r;
}
__device__ __forceinline__ void unpack2(ull v, float& lo, float& hi) {
    asm("mov.b64 {%0, %1}, %2;" : "=f"(lo), "=f"(hi) : "l"(v));
}
__device__ __forceinline__ void dfma(ull& acc, ull a, ull b) {
    asm("fma.rn.f32x2 %0, %1, %2, %0;" : "+l"(acc) : "l"(a), "l"(b));
}
__device__ __forceinline__ ull addx2(ull a, ull b) {
    ull r; asm("add.rn.f32x2 %0, %1, %2;" : "=l"(r) : "l"(a), "l"(b)); return r;
}
__device__ __forceinline__ void gemm_row(ull* y, ull a, const float* wrow) {
    const longlong2* w = (const longlong2*)wrow;
#pragma unroll
    for (int k8 = 0; k8 < 8; k8++) {
        longlong2 v = w[k8];
        dfma(y[2 * k8 + 0], a, (ull)v.x);
        dfma(y[2 * k8 + 1], a, (ull)v.y);
    }
}
__device__ __forceinline__ void cp16(float* sdst, const float4* gsrc) {
    unsigned s = (unsigned)__cvta_generic_to_shared(sdst);
    asm volatile("cp.async.cg.shared.global [%0], [%1], 16;" :: "r"(s), "l"(gsrc));
}

// ---------------- smem layout (floats) ----------------
#define OFF_W     0          // 6144 : Wc1 (first 3072) then Wc2 [6][32][32]
#define OFF_T0    6144       // 8192 : tile0 (layer1 scratch aliases here)
#define OFF_T1    14336      // 8192 : tile1
#define OFF_GT    22528      // 1728 : sGt triple buffer [3][16][36]
#define OFF_DG    24256      // 1728 : sDiag triple buffer
#define OFF_SAB   25984      // 512
#define OFF_STB   26496      // 512
#define OFF_SAL   27008      // 32
#define OFF_YB    27040      // 1088 : ull[2][272]; OVERLAY: sU(512)+sD(32)+sRED(32) post-pickup
#define OFF_INT   28128      // nbr16,qm16,vm16,cnt16,misc4,M(64w) = 132 floats
#define SMEM_FLOATS (28128 + 132)
#define SMEM_BYTES  (SMEM_FLOATS * 4)

__device__ __forceinline__ void issue_tile(int t, float* buf, int tid, const int* sNbr) {
    const float4* src = (const float4*)(g_F1 + (size_t)sNbr[t] * 8192);
#pragma unroll
    for (int k = 0; k < 8; k++) {
        int g = k * 256 + tid;
        int r = g >> 3, c4 = g & 7;
        cp16(buf + r * 32 + ((c4 ^ (r & 7)) << 2), src + g);
    }
    asm volatile("cp.async.commit_group;");
}

// pair-tile collaborative gb/dg gemm: thread (i,j) computes h-pair j of row i for two tiles,
// sharing the weight fetches between them.
__device__ __forceinline__ void collab_pair(const float* gA, const float* dA,
                                            const float* gB, const float* dB,
                                            const float* w0b, const float* w5b,
                                            ull* outA, ull* outB) {
    ull a0 = 0, a1 = 0, b0 = 0, b1 = 0;
#pragma unroll
    for (int c4 = 0; c4 < 8; c4++) {
        float4 ga = *(const float4*)(gA + c4 * 4);
        float4 da = *(const float4*)(dA + c4 * 4);
        float4 gb = *(const float4*)(gB + c4 * 4);
        float4 db = *(const float4*)(dB + c4 * 4);
        float gav[4] = {ga.x, ga.y, ga.z, ga.w};
        float dav[4] = {da.x, da.y, da.z, da.w};
        float gbv[4] = {gb.x, gb.y, gb.z, gb.w};
        float dbv[4] = {db.x, db.y, db.z, db.w};
#pragma unroll
        for (int cl = 0; cl < 4; cl++) {
            int c = c4 * 4 + cl;
            ull w0 = *(const ull*)(w0b + c * 32);
            ull w5 = *(const ull*)(w5b + c * 32);
            dfma(a0, pack2(gav[cl]), w0);
            dfma(b0, pack2(gbv[cl]), w0);
            dfma(a1, pack2(dav[cl]), w5);
            dfma(b1, pack2(dbv[cl]), w5);
        }
    }
    *outA = addx2(a0, a1);
    *outB = addx2(b0, b1);
}

__device__ __forceinline__ void phaseA(int t, const float4* bufv, float* sGt, float* sDg,
                                       const unsigned* sQM, const signed char* sM,
                                       int aA, int half, int c4A, ull& stbA, ull& stbB) {
    int par = (t % 3) * 576;
    unsigned qm = sQM[t];
    int pA = sM[t * 16 + aA];
    ull acc0 = 0ull, acc1 = 0ull;
    if (pA >= 0) {
        int rbase = pA * 16 + half * 8;
#pragma unroll
        for (int k = 0; k < 8; k++) {
            if (qm & (1u << (half * 8 + k))) {
                int r = rbase + k;
                longlong2 v = *(const longlong2*)(bufv + r * 8 + (c4A ^ (r & 7)));
                acc0 = addx2(acc0, (ull)v.x);
                acc1 = addx2(acc1, (ull)v.y);
            }
        }
    }
    float f0, f1, f2, f3;
    unpack2(acc0, f0, f1);
    unpack2(acc1, f2, f3);
    f0 += __shfl_xor_sync(0xffffffffu, f0, 8);
    f1 += __shfl_xor_sync(0xffffffffu, f1, 8);
    f2 += __shfl_xor_sync(0xffffffffu, f2, 8);
    f3 += __shfl_xor_sync(0xffffffffu, f3, 8);
    stbA = addx2(stbA, pack2f(f0, f1));
    stbB = addx2(stbB, pack2f(f2, f3));
    if (half == 0) {
        float4 o; o.x = f0; o.y = f1; o.z = f2; o.w = f3;
        *(float4*)(sGt + par + aA * 36 + c4A * 4) = o;
    } else {
        longlong2 dv; dv.x = 0; dv.y = 0;
        if (pA >= 0) {
            int rd = pA * 17;
            dv = *(const longlong2*)(bufv + rd * 8 + (c4A ^ (rd & 7)));
        }
        *(longlong2*)(sDg + par + aA * 36 + c4A * 4) = dv;
    }
}

__device__ __forceinline__ void stGather(int t, const float4* bufv, const signed char* sM,
                                         int i, int j, ull* st2) {
    int pa = sM[t * 16 + i], pb = sM[t * 16 + j];
    if ((pa | pb) >= 0) {
        int r = pa * 16 + pb;
#pragma unroll
        for (int c4 = 0; c4 < 8; c4++) {
            longlong2 v = *(const longlong2*)(bufv + r * 8 + (c4 ^ (r & 7)));
            st2[2 * c4 + 0] = addx2(st2[2 * c4 + 0], (ull)v.x);
            st2[2 * c4 + 1] = addx2(st2[2 * c4 + 1], (ull)v.y);
        }
    }
}

__global__ __launch_bounds__(256, 2) void ccn_fused(const int* __restrict__ nbrs,
                                                    const float* __restrict__ X,
                                                    const float* __restrict__ W1,
                                                    const float* __restrict__ b1,
                                                    const float* __restrict__ W2,
                                                    const float* __restrict__ b2,
                                                    const float* __restrict__ fcw,
                                                    const float* __restrict__ fcb,
                                                    float* __restrict__ out) {
    extern __shared__ float smem[];
    float* sW    = smem + OFF_W;
    float* tile0 = smem + OFF_T0;
    float* tile1 = smem + OFF_T1;
    float* sGt   = smem + OFF_GT;    // [3][16][36]
    float* sDg   = smem + OFF_DG;    // [3][16][36]
    float* sSAB  = smem + OFF_SAB;   // [16][32]
    float* sSTB  = smem + OFF_STB;   // [16][32]
    float* sSAL  = smem + OFF_SAL;
    ull*   sYB   = (ull*)(smem + OFF_YB);     // [2][272]; overlaid by sU/sD/sRED later
    float* sU    = smem + OFF_YB;             // valid after pickup barrier
    float* sD    = sU + 512;
    float* sRED  = sU + 544;
    int*      sNbr = (int*)(smem + OFF_INT);
    unsigned* sQM  = (unsigned*)(sNbr + 16);
    unsigned* sVM  = (unsigned*)(sQM + 16);
    float*    sCnt = (float*)(sVM + 16);
    unsigned* sMisc = (unsigned*)(sCnt + 16);
    signed char* sM = (signed char*)(sMisc + 4);     // 256

    // layer-1 scratch aliases inside tile0
    float* sXn  = tile0;          // 256
    float* sAB1 = tile0 + 256;    // 256
    float* sTB1 = tile0 + 512;    // 256
    float* sAL1 = tile0 + 768;    // 16
    float* sU1  = tile0 + 784;    // 512
    float* sD1  = tile0 + 1296;   // 32
    float* sB1  = tile0 + 1328;   // 32
    float* sR   = tile0 + 1360;   // 512 : per-row xv-term table
    float* sZ   = tile0 + 1872;   // 512 : Z = Xn @ W2b

    int n = blockIdx.x, tid = threadIdx.x;
    int i = tid >> 4, j = tid & 15;
    int aA = i;                    // phase-A row
    int half = (tid >> 3) & 1;     // phase-A q-half
    int c4A = tid & 7;             // phase-A float4 column

    // ============ stage 0 ============
    {
        int jv = nbrs[n * 16 + i];
        int target = nbrs[n * 16 + j];
        int r = -1;
#pragma unroll
        for (int p = 0; p < 16; p++)
            if (nbrs[jv * 16 + p] == target) r = p;
        sM[tid] = (signed char)r;                 // sM[t*16+a], t=i, a=j
        sXn[tid] = X[jv * 16 + j];
    }
    if (tid < 16) sNbr[tid] = nbrs[n * 16 + tid];
    // Wc1 (C=16): slot0=16*(W0+W6..14)+W5, 1=W1, 2=16*W2, 3=W3, 4=W4, 5=W15
    for (int idx = tid; idx < 512; idx += 256) {
        int c = idx >> 5, h = idx & 31;
        float s = W1[(0 * 16 + c) * 32 + h];
#pragma unroll
        for (int m = 6; m < 15; m++) s += W1[(m * 16 + c) * 32 + h];
        sW[0 * 512 + c * 32 + h] = 16.0f * s + W1[(5 * 16 + c) * 32 + h];
        sW[1 * 512 + c * 32 + h] = W1[(1 * 16 + c) * 32 + h];
        sW[2 * 512 + c * 32 + h] = 16.0f * W1[(2 * 16 + c) * 32 + h];
        sW[3 * 512 + c * 32 + h] = W1[(3 * 16 + c) * 32 + h];
        sW[4 * 512 + c * 32 + h] = W1[(4 * 16 + c) * 32 + h];
        sW[5 * 512 + c * 32 + h] = W1[(15 * 16 + c) * 32 + h];
    }
    if (tid < HD) sB1[tid] = b1[tid];
    if (tid == 0) sMisc[0] = g_epoch;
    __syncthreads();
    if (tid < 16) {
        unsigned vm = 0, qm = 0;
#pragma unroll
        for (int a = 0; a < 16; a++) {
            int p = sM[tid * 16 + a];
            if (p >= 0) { vm |= 1u << a; qm |= 1u << p; }
        }
        sVM[tid] = vm;
        sQM[tid] = qm;
        sCnt[tid] = (float)__popc(vm);
    }
    __syncthreads();

    // ============ layer 1 (F0[n,p,q,c] = X[n,c] closed forms + row-shared tables) ============
    sAB1[tid] = sCnt[i] * sCnt[i] * sXn[tid];
    {
        float s = 0.0f;
#pragma unroll
        for (int t = 0; t < 16; t++)
            if ((sVM[t] >> i) & 1) s += sCnt[t] * sXn[t * 16 + j];
        sTB1[tid] = s;
    }
    // R[row][h] = cnt_row*(Xn_row @ Wsb)[h] + (Xn_row @ W15)[h];  Z[row][h] = (Xn_row @ W2b)[h]
#pragma unroll
    for (int rep = 0; rep < 2; rep++) {
        int idx = tid + rep * 256;
        int row = idx >> 5, h = idx & 31;
        float a1 = 0.0f, a2 = 0.0f, zz = 0.0f;
#pragma unroll
        for (int c = 0; c < 16; c++) {
            float xv = sXn[row * 16 + c];
            a1 += xv * sW[0 * 512 + c * 32 + h];
            zz += xv * sW[2 * 512 + c * 32 + h];
            a2 += xv * sW[5 * 512 + c * 32 + h];
        }
        sR[idx] = sCnt[row] * a1 + a2;
        sZ[idx] = zz;
    }
    __syncthreads();
    if (tid < 16) {
        float s = 0.0f;
#pragma unroll
        for (int t = 0; t < 16; t++) s += sAB1[t * 16 + tid];
        sAL1[tid] = s;
    }
    __syncthreads();
    {
        int r0 = tid >> 5, h = tid & 31;
        float ua = 0.0f, ub = 0.0f;
#pragma unroll
        for (int c = 0; c < 16; c++) {
            float w1b = sW[1 * 512 + c * 32 + h];
            float w3b = sW[3 * 512 + c * 32 + h];
            ua += sAB1[r0 * 16 + c] * w1b + sTB1[r0 * 16 + c] * w3b;
            ub += sAB1[(r0 + 8) * 16 + c] * w1b + sTB1[(r0 + 8) * 16 + c] * w3b;
        }
        sU1[r0 * 32 + h] = ua;
        sU1[(r0 + 8) * 32 + h] = ub;
    }
    if (tid < HD) {
        float s = 0.0f;
#pragma unroll
        for (int c = 0; c < 16; c++) s += sAL1[c] * sW[4 * 512 + c * 32 + tid];
        sD1[tid] = s;
    }
    __syncthreads();
    {   // y1 = U1 + b1 + delta*D1 + valid*R[i] + sum_t p_ij[t]*Z[t]
        ull y1[16];
#pragma unroll
        for (int k = 0; k < 16; k++) {
            ull u = *(const ull*)(sU1 + i * 32 + 2 * k);
            ull b = *(const ull*)(sB1 + 2 * k);
            y1[k] = addx2(u, b);
            if (i == j) y1[k] = addx2(y1[k], *(const ull*)(sD1 + 2 * k));
        }
        if (sM[i * 16 + j] >= 0) {
            const longlong2* rr = (const longlong2*)(sR + i * 32);
#pragma unroll
            for (int k8 = 0; k8 < 8; k8++) {
                longlong2 v = rr[k8];
                y1[2 * k8 + 0] = addx2(y1[2 * k8 + 0], (ull)v.x);
                y1[2 * k8 + 1] = addx2(y1[2 * k8 + 1], (ull)v.y);
            }
        }
#pragma unroll
        for (int t = 0; t < 16; t++) {
            unsigned vm = sVM[t];
            if (((vm >> i) & (vm >> j)) & 1) {
                const longlong2* zr = (const longlong2*)(sZ + t * 32);
#pragma unroll
                for (int k8 = 0; k8 < 8; k8++) {
                    longlong2 v = zr[k8];
                    y1[2 * k8 + 0] = addx2(y1[2 * k8 + 0], (ull)v.x);
                    y1[2 * k8 + 1] = addx2(y1[2 * k8 + 1], (ull)v.y);
                }
            }
        }
        float* dst = g_F1 + (size_t)(n * 256 + tid) * 32;
#pragma unroll
        for (int q = 0; q < 8; q++) {
            float4 o;
            unpack2(y1[2 * q + 0], o.x, o.y);
            unpack2(y1[2 * q + 1], o.z, o.w);
            o.x = fmaxf(o.x, 0.0f); o.y = fmaxf(o.y, 0.0f);
            o.z = fmaxf(o.z, 0.0f); o.w = fmaxf(o.w, 0.0f);
            ((float4*)dst)[q] = o;
        }
    }
    __threadfence();
    __syncthreads();
    if (tid == 0) atomicExch(&g_flag[n], sMisc[0] + 1);   // publish

    // ============ Wc2 (C=32) ============
    for (int idx = tid; idx < 1024; idx += 256) {
        int c = idx >> 5, h = idx & 31;
        float s = W2[(0 * 32 + c) * 32 + h];
#pragma unroll
        for (int m = 6; m < 15; m++) s += W2[(m * 32 + c) * 32 + h];
        sW[0 * 1024 + c * 32 + h] = 16.0f * s + W2[(5 * 32 + c) * 32 + h];
        sW[1 * 1024 + c * 32 + h] = W2[(1 * 32 + c) * 32 + h];
        sW[2 * 1024 + c * 32 + h] = 16.0f * W2[(2 * 32 + c) * 32 + h];
        sW[3 * 1024 + c * 32 + h] = W2[(3 * 32 + c) * 32 + h];
        sW[4 * 1024 + c * 32 + h] = W2[(4 * 32 + c) * 32 + h];
        sW[5 * 1024 + c * 32 + h] = W2[(15 * 32 + c) * 32 + h];
    }
    if (tid < 16) {
        unsigned tgt = sMisc[0] + 1;
        const unsigned* fp = &g_flag[sNbr[tid]];
        unsigned v;
        do {
            asm volatile("ld.acquire.gpu.global.u32 %0, [%1];" : "=r"(v) : "l"(fp) : "memory");
        } while (v != tgt);
    }
    __syncthreads();

    // ============ layer 2 main loop (pair-collab on even iterations) ============
    issue_tile(0, tile0, tid, sNbr);

    ull st2[16];
#pragma unroll
    for (int c = 0; c < 16; c++) st2[c] = 0ull;
    ull y[16];
#pragma unroll
    for (int k = 0; k < 16; k++) y[k] = 0ull;
    ull stbA = 0ull, stbB = 0ull;

    for (int tt = 0; tt < 8; tt++) {
        int t0 = 2 * tt, t1 = 2 * tt + 1;
        // ---- even iteration t0 (tile in tile0) ----
        {
            const float4* bufv = (const float4*)tile0;
            asm volatile("cp.async.wait_group 0;");
            __syncthreads();
            issue_tile(t1, tile1, tid, sNbr);
            if (tt >= 1) {      // collab for tiles t0-1, t0-2 (slots disjoint from t0%3)
                int sA = ((t0 - 1) % 3) * 576, sB = ((t0 - 2) % 3) * 576;
                collab_pair(sGt + sA + i * 36, sDg + sA + i * 36,
                            sGt + sB + i * 36, sDg + sB + i * 36,
                            sW + 2 * j, sW + 5 * 1024 + 2 * j,
                            &sYB[i * 17 + j], &sYB[272 + i * 17 + j]);
            }
            phaseA(t0, bufv, sGt, sDg, sQM, sM, aA, half, c4A, stbA, stbB);
            stGather(t0, bufv, sM, i, j, st2);
            if (tt >= 1 && tid < 32) {
                const float* gp = sGt + ((t0 - 1) % 3) * 576;
                float s = 0.0f;
#pragma unroll
                for (int a = 0; a < 16; a++) s += gp[a * 36 + tid];
                sSAB[(t0 - 1) * 32 + tid] = s;
            }
        }
        // ---- odd iteration t1 (tile in tile1) ----
        {
            const float4* bufv = (const float4*)tile1;
            asm volatile("cp.async.wait_group 0;");
            __syncthreads();
            if (t1 < 15) issue_tile(t1 + 1, tile0, tid, sNbr);
            if (tt >= 1) {      // pickup tiles collabed this tt: t0-1 (slot0), t0-2 (slot1)
                if (i == t0 - 1) {
#pragma unroll
                    for (int k = 0; k < 16; k++) y[k] = addx2(y[k], sYB[j * 17 + k]);
                }
                if (i == t0 - 2) {
#pragma unroll
                    for (int k = 0; k < 16; k++) y[k] = addx2(y[k], sYB[272 + j * 17 + k]);
                }
            }
            phaseA(t1, bufv, sGt, sDg, sQM, sM, aA, half, c4A, stbA, stbB);
            stGather(t1, bufv, sM, i, j, st2);
            if (tid < 32) {
                const float* gp = sGt + (t0 % 3) * 576;
                float s = 0.0f;
#pragma unroll
                for (int a = 0; a < 16; a++) s += gp[a * 36 + tid];
                sSAB[t0 * 32 + tid] = s;
            }
        }
    }

    // ============ epilogue ============
    __syncthreads();                           // E1: phase A(15/14) visible
    collab_pair(sGt + 0 * 576 + i * 36, sDg + 0 * 576 + i * 36,    // tile 15 (15%3=0)
                sGt + 2 * 576 + i * 36, sDg + 2 * 576 + i * 36,    // tile 14 (14%3=2)
                sW + 2 * j, sW + 5 * 1024 + 2 * j,
                &sYB[i * 17 + j], &sYB[272 + i * 17 + j]);
    if (tid < 32) {                            // sum_ab(15)
        const float* gp = sGt + 0 * 576;
        float s = 0.0f;
#pragma unroll
        for (int a = 0; a < 16; a++) s += gp[a * 36 + tid];
        sSAB[15 * 32 + tid] = s;
    }
    if (half == 0) {                           // write sum_tb
        float4 o;
        unpack2(stbA, o.x, o.y);
        unpack2(stbB, o.z, o.w);
        *(float4*)(sSTB + aA * 32 + c4A * 4) = o;
    }
    __syncthreads();                           // E2
    if (i == 15) {
#pragma unroll
        for (int k = 0; k < 16; k++) y[k] = addx2(y[k], sYB[j * 17 + k]);
    }
    if (i == 14) {
#pragma unroll
        for (int k = 0; k < 16; k++) y[k] = addx2(y[k], sYB[272 + j * 17 + k]);
    }
    if (tid < 32) {
        float s = 0.0f;
#pragma unroll
        for (int t = 0; t < 16; t++) s += sSAB[t * 32 + tid];
        sSAL[tid] = s;
    }
    __syncthreads();                           // E3: sYB reads done; overlay now writable
    {   // U[row][h] into overlay
        int r0 = tid >> 5, h = tid & 31;
        float ua = 0.0f, ub = 0.0f;
#pragma unroll
        for (int c = 0; c < 32; c++) {
            float w1b = sW[1 * 1024 + c * 32 + h];
            float w3b = sW[3 * 1024 + c * 32 + h];
            ua += sSAB[r0 * 32 + c] * w1b + sSTB[r0 * 32 + c] * w3b;
            ub += sSAB[(r0 + 8) * 32 + c] * w1b + sSTB[(r0 + 8) * 32 + c] * w3b;
        }
        sU[r0 * 32 + h] = ua;
        sU[(r0 + 8) * 32 + h] = ub;
    }
    if (tid < 32) {
        float d = 0.0f;
#pragma unroll
        for (int c = 0; c < 32; c++) d += sSAL[c] * sW[4 * 1024 + c * 32 + tid];
        sD[tid] = d;
    }
    __syncthreads();                           // E4

    // ---- st GEMM (W2b, broadcast weights) ----
#pragma unroll
    for (int cc = 0; cc < 16; cc++) {
        float lo, hi;
        unpack2(st2[cc], lo, hi);
        gemm_row(y, pack2(lo), sW + 2 * 1024 + (2 * cc + 0) * 32);
        gemm_row(y, pack2(hi), sW + 2 * 1024 + (2 * cc + 1) * 32);
    }

    // ---- finalize: add U/D/bias(global), relu, dot fc(global), reduce ----
    float loc = 0.0f;
    const ull* b2p = (const ull*)b2;
    const ull* fwp = (const ull*)fcw;
#pragma unroll
    for (int k = 0; k < 16; k++) {
        ull u = *(const ull*)(sU + i * 32 + 2 * k);
        ull v = addx2(y[k], addx2(u, b2p[k]));
        if (i == j) v = addx2(v, *(const ull*)(sD + 2 * k));
        float lo, hi;
        unpack2(v, lo, hi);
        float w0, w1;
        unpack2(fwp[k], w0, w1);
        loc += fmaxf(lo, 0.0f) * w0 + fmaxf(hi, 0.0f) * w1;
    }
#pragma unroll
    for (int o = 16; o > 0; o >>= 1) loc += __shfl_xor_sync(0xffffffffu, loc, o);
    if ((tid & 31) == 0) sRED[tid >> 5] = loc;
    __syncthreads();
    if (tid == 0) {
        float s = 0.0f;
#pragma unroll
        for (int w = 0; w < 8; w++) s += sRED[w];
        atomicAdd(&g_acc, s);
        __threadfence();
        unsigned prev = atomicAdd(&g_done, 1);
        if (prev == NV - 1) {
            float tot = atomicAdd(&g_acc, 0.0f);
            out[0] = tot + fcb[0];
            g_acc = 0.0f;
            g_done = 0;
            g_epoch = sMisc[0] + 1;
            __threadfence();
        }
    }
}

extern "C" void kernel_launch(void* const* d_in, const int* in_sizes, int n_in,
                              void* d_out, int out_size) {
    const float* X   = (const float*)d_in[0];
    const int*   nbr = (const int*)d_in[1];
    const float* W1  = (const float*)d_in[2];
    const float* b1  = (const float*)d_in[3];
    const float* W2  = (const float*)d_in[4];
    const float* b2  = (const float*)d_in[5];
    const float* fcw = (const float*)d_in[6];
    const float* fcb = (const float*)d_in[7];
    float* out = (float*)d_out;

    cudaFuncSetAttribute(ccn_fused, cudaFuncAttributeMaxDynamicSharedMemorySize, SMEM_BYTES);
    ccn_fused<<<NV, 256, SMEM_BYTES>>>(nbr, X, W1, b1, W2, b2, fcw, fcb, out);
}